// round 3
// baseline (speedup 1.0000x reference)
#include <cuda_runtime.h>
#include <cstdint>

// TopK per row (B x D fp32, top-k along D, ReLU, scatter into zeros).
// One CTA per row. Hot path: single streaming pass that
//   - reads the row (LDG.128, streaming, 8-deep batched for MLP)
//   - writes zeros to the output row (STG.128, streaming)
//   - collects candidates >= THRESH (conservative static threshold) into smem
// then exact-ranks the ~400 candidates in smem and scatters the k winners.
// Exact fallback (full 4096-bin histogram selection) runs iff the candidate
// count is < k or overflows; never triggers on the benchmark distribution
// but keeps the kernel exact for arbitrary inputs.

namespace {

constexpr int TPB    = 512;
constexpr int D_DIM  = 65536;
constexpr int NV     = D_DIM / 4;      // float4 vectors per row (16384)
constexpr int UNROLL = 8;              // batched loads per thread per iter
constexpr int NB     = 4096;           // fallback histogram bins (12-bit key)
constexpr int SEG    = NB / TPB;       // 8
constexpr int CAP    = 4096;           // candidate capacity
constexpr float THRESH = 2.5f;         // conservative: E[cnt]~407 >> k=64
constexpr unsigned SMEM_BYTES = 3u * 4096u * 4u;   // 48 KB dynamic

__device__ __forceinline__ unsigned orderKey(float f) {
    unsigned u = __float_as_uint(f);
    return u ^ ((u & 0x80000000u) ? 0xFFFFFFFFu : 0x80000000u);
}
__device__ __forceinline__ float keyToFloat(unsigned key) {
    unsigned u = (key & 0x80000000u) ? (key ^ 0x80000000u) : ~key;
    return __uint_as_float(u);
}

__global__ void __launch_bounds__(TPB, 4)
topk_thresh_kernel(const float* __restrict__ x,
                   const int* __restrict__ kptr,
                   float* __restrict__ out)
{
    extern __shared__ unsigned smem_u[];
    float*    cval = reinterpret_cast<float*>(smem_u);    // [CAP]
    unsigned* cidx = smem_u + CAP;                        // [CAP]
    unsigned* hist = smem_u + 2 * CAP;                    // [NB] fallback only
    __shared__ unsigned s_cnt, s_bin, s_rank;

    const int tid = threadIdx.x;
    const int row = blockIdx.x;
    const unsigned k = (unsigned)__ldg(kptr);

    const float4* rowv = reinterpret_cast<const float4*>(x) + (size_t)row * NV;
    float4*       outv = reinterpret_cast<float4*>(out)     + (size_t)row * NV;

    if (tid == 0) s_cnt = 0u;
    __syncthreads();

    // ---- Hot pass: batched stream read + zero write + rare collect ----
    const float4 z = make_float4(0.f, 0.f, 0.f, 0.f);
    // NV / (TPB*UNROLL) = 16384 / 4096 = 4 outer iterations, exact fit.
    for (int base = tid; base < NV; base += TPB * UNROLL) {
        float4 v[UNROLL];
        #pragma unroll
        for (int u = 0; u < UNROLL; ++u)
            v[u] = __ldcs(&rowv[base + u * TPB]);
        #pragma unroll
        for (int u = 0; u < UNROLL; ++u)
            __stcs(&outv[base + u * TPB], z);
        #pragma unroll
        for (int u = 0; u < UNROLL; ++u) {
            float m = fmaxf(fmaxf(v[u].x, v[u].y), fmaxf(v[u].z, v[u].w));
            if (m >= THRESH) {                       // rare (~1 in 40 vectors)
                const int i = base + u * TPB;
                float vv[4] = {v[u].x, v[u].y, v[u].z, v[u].w};
                #pragma unroll
                for (int l = 0; l < 4; ++l) {
                    if (vv[l] >= THRESH) {
                        unsigned p = atomicAdd(&s_cnt, 1u);
                        if (p < CAP) { cval[p] = vv[l]; cidx[p] = (unsigned)(i * 4 + l); }
                    }
                }
            }
        }
    }
    __syncthreads();

    const unsigned cnt = s_cnt;

    if (cnt >= k && cnt <= CAP) {
        // ---- Exact rank among candidates (all of top-k are here) ----
        for (unsigned j = (unsigned)tid; j < cnt; j += TPB) {
            const float    vj = cval[j];
            const unsigned ij = cidx[j];
            unsigned rank = 0;
            for (unsigned t = 0; t < cnt; ++t) {
                const float vt = cval[t];
                rank += (vt > vj) || (vt == vj && cidx[t] < ij);
            }
            if (rank < k)
                out[(size_t)row * D_DIM + ij] = fmaxf(vj, 0.0f);
        }
        return;
    }

    // ================= Exact fallback (histogram selection) =================
    // Runs only for rows where the static threshold failed.
    for (int i = tid; i < NB; i += TPB) hist[i] = 0u;
    __syncthreads();

    for (int i = tid; i < NV; i += TPB) {
        float4 v = __ldcs(&rowv[i]);
        atomicAdd(&hist[orderKey(v.x) >> 20], 1u);
        atomicAdd(&hist[orderKey(v.y) >> 20], 1u);
        atomicAdd(&hist[orderKey(v.z) >> 20], 1u);
        atomicAdd(&hist[orderKey(v.w) >> 20], 1u);
    }
    __syncthreads();

    // suffix scan over 512 segment partials (scratch aliases cval region)
    unsigned* partial = reinterpret_cast<unsigned*>(cval);
    {
        unsigned s = 0;
        #pragma unroll
        for (int j = 0; j < SEG; ++j) s += hist[tid * SEG + j];
        partial[tid] = s;
    }
    __syncthreads();
    for (int off = 1; off < TPB; off <<= 1) {
        unsigned v = partial[tid];
        unsigned a = (tid + off < TPB) ? partial[tid + off] : 0u;
        __syncthreads();
        partial[tid] = v + a;
        __syncthreads();
    }
    {
        unsigned St = partial[tid];
        unsigned Sn = (tid + 1 < TPB) ? partial[tid + 1] : 0u;
        if (St >= k && Sn < k) {
            unsigned acc = Sn;
            #pragma unroll
            for (int j = SEG - 1; j >= 0; --j) {
                unsigned c = hist[tid * SEG + j];
                if (acc + c >= k) { s_bin = (unsigned)(tid * SEG + j); s_rank = k - acc; break; }
                acc += c;
            }
        }
    }
    __syncthreads();
    const unsigned bcrit = s_bin;
    const unsigned rneed = s_rank;

    if (tid == 0) s_cnt = 0u;
    __syncthreads();

    // scatter definite winners; collect critical-bin candidates
    for (int i = tid; i < NV; i += TPB) {
        float4 v = __ldcs(&rowv[i]);
        float vv[4] = {v.x, v.y, v.z, v.w};
        #pragma unroll
        for (int l = 0; l < 4; ++l) {
            unsigned key = orderKey(vv[l]);
            unsigned bin = key >> 20;
            if (bin > bcrit) {
                out[(size_t)row * D_DIM + i * 4 + l] = fmaxf(vv[l], 0.0f);
            } else if (bin == bcrit) {
                unsigned p = atomicAdd(&s_cnt, 1u);
                if (p < CAP) {
                    reinterpret_cast<unsigned*>(cval)[p] = key;   // store KEY here
                    cidx[p] = (unsigned)(i * 4 + l);
                }
            }
        }
    }
    __syncthreads();

    const unsigned ccnt = min(s_cnt, (unsigned)CAP);
    const unsigned* ckey = reinterpret_cast<const unsigned*>(cval);
    for (unsigned j = (unsigned)tid; j < ccnt; j += TPB) {
        const unsigned kj = ckey[j], ij = cidx[j];
        unsigned rank = 0;
        for (unsigned t = 0; t < ccnt; ++t) {
            const unsigned kt = ckey[t];
            rank += (kt > kj) || (kt == kj && cidx[t] < ij);
        }
        if (rank < rneed)
            out[(size_t)row * D_DIM + ij] = fmaxf(keyToFloat(kj), 0.0f);
    }
}

} // namespace

extern "C" void kernel_launch(void* const* d_in, const int* in_sizes, int n_in,
                              void* d_out, int out_size)
{
    const float* x   = (const float*)d_in[0];
    const int*   kp  = (const int*)d_in[1];
    float*       out = (float*)d_out;

    const int rows = in_sizes[0] / D_DIM;

    cudaFuncSetAttribute(topk_thresh_kernel,
                         cudaFuncAttributeMaxDynamicSharedMemorySize, SMEM_BYTES);
    topk_thresh_kernel<<<rows, TPB, SMEM_BYTES>>>(x, kp, out);
}